// round 12
// baseline (speedup 1.0000x reference)
#include <cuda_runtime.h>
#include <cuda_bf16.h>
#include <math.h>
#include <stdint.h>

// Problem constants: B=16,T=128 -> 2048 graphs; J=75; 3->64->256; E=300.
#define NJ    75
#define DIN   3
#define HID   64
#define NOUT  256
#define MAX_E 1024
#define MAX_T 544
#define MAXG  2048

// ---------------- persistent device scratch ----------------
__device__ int   g_csr_src[MAX_T];
__device__ float g_csr_w[MAX_T];
__device__ int   g_csr_off[NJ + 1];
__device__ __nv_bfloat16 g_ah_hi[MAXG * NJ * HID];   // ah1 split hi [row][k]
__device__ __nv_bfloat16 g_ah_lo[MAXG * NJ * HID];   // ah1 split lo
__device__ __nv_bfloat16 g_w2t_hi[NOUT * HID];       // W2^T split hi [n][k]
__device__ __nv_bfloat16 g_w2t_lo[NOUT * HID];       // W2^T split lo

// ---------------- math helpers ----------------
__device__ __forceinline__ float gelu_fast(float v) {
    const float x  = v * 0.70710678118654752f;
    const float ax = fabsf(x);
    const float den = fmaf(0.3275911f, ax, 1.0f);
    const float t   = __frcp_rn(den);
    float p = fmaf(1.061405429f, t, -1.453152027f);
    p = fmaf(p, t, 1.421413741f);
    p = fmaf(p, t, -0.284496736f);
    p = fmaf(p, t, 0.254829592f);
    p = p * t;
    const float ex   = __expf(-x * x);
    const float erfa = fmaf(-p, ex, 1.0f);
    return 0.5f * v * (1.0f + copysignf(erfa, x));
}
__device__ __forceinline__ int clampj(int v) {
    return v < 0 ? 0 : (v >= NJ ? NJ - 1 : v);
}

// Classic warp-level bf16 MMA (sm_80+ PTX, legal on plain sm_103 target).
#define MMA_BF16(d, a0, a1, a2, a3, b0, b1)                                   \
    asm volatile("mma.sync.aligned.m16n8k16.row.col.f32.bf16.bf16.f32 "       \
        "{%0,%1,%2,%3}, {%4,%5,%6,%7}, {%8,%9}, {%0,%1,%2,%3};"               \
        : "+f"((d)[0]), "+f"((d)[1]), "+f"((d)[2]), "+f"((d)[3])              \
        : "r"(a0), "r"(a1), "r"(a2), "r"(a3), "r"(b0), "r"(b1))

// ---------------------------------------------------------------------------
// W2^T bf16 hi/lo split — multi-block (was latency-bound on 1 block).
// ---------------------------------------------------------------------------
__global__ void prep_w2(const float* __restrict__ W2) {
    int i = blockIdx.x * blockDim.x + threadIdx.x;
    if (i < NOUT * HID) {
        int n = i >> 6, k = i & 63;
        float f = W2[k * NOUT + n];
        __nv_bfloat16 h = __float2bfloat16(f);
        __nv_bfloat16 l = __float2bfloat16(f - __bfloat162float(h));
        g_w2t_hi[i] = h;
        g_w2t_lo[i] = l;
    }
}

// ---------------------------------------------------------------------------
// CSR of normalized adjacency. One block (small).
// ---------------------------------------------------------------------------
__global__ void __launch_bounds__(256)
setup_csr(const void* __restrict__ eiv, int E) {
    const int*       e32 = (const int*)eiv;
    const long long* e64 = (const long long*)eiv;

    __shared__ int   s_odd;
    __shared__ int   s_src[MAX_E];
    __shared__ int   s_dst[MAX_E];
    __shared__ int   s_deg[NJ];
    __shared__ float s_dis[NJ];
    __shared__ int   s_off[NJ + 1];

    const int t = threadIdx.x;

    if (t == 0) s_odd = 0;
    __syncthreads();
    {
        int local = 0;
        for (int i = 2 * t + 1; i < 2 * E; i += 2 * blockDim.x)
            local |= (e32[i] != 0);
        if (local) atomicOr(&s_odd, 1);
    }
    __syncthreads();
    const int is64 = !s_odd;

    for (int i = t; i < E; i += blockDim.x) {
        int sv, dv;
        if (is64) { sv = (int)e64[i]; dv = (int)e64[E + i]; }
        else      { sv = e32[i];      dv = e32[E + i]; }
        s_src[i] = clampj(sv);
        s_dst[i] = clampj(dv);
    }
    for (int j = t; j < NJ; j += blockDim.x) s_deg[j] = 1;  // self loop
    __syncthreads();
    for (int i = t; i < E; i += blockDim.x) atomicAdd(&s_deg[s_dst[i]], 1);
    __syncthreads();
    if (t == 0) {
        int acc = 0;
        for (int j = 0; j < NJ; j++) { s_off[j] = acc; acc += s_deg[j]; }
        s_off[NJ] = acc;
    }
    for (int j = t; j < NJ; j += blockDim.x) s_dis[j] = rsqrtf((float)s_deg[j]);
    __syncthreads();
    if (t < NJ) {
        int p = s_off[t];
        float dj = s_dis[t];
        for (int e = 0; e < E; e++) {
            if (s_dst[e] == t) {
                int se = s_src[e];
                g_csr_src[p] = se;
                g_csr_w[p]   = s_dis[se] * dj;
                p++;
            }
        }
        g_csr_src[p] = t;               // self loop last (reference order)
        g_csr_w[p]   = dj * dj;
    }
    for (int j = t; j <= NJ; j += blockDim.x) g_csr_off[j] = s_off[j];
}

// ---------------------------------------------------------------------------
// Part A (per-graph CTA): ah1 = A * gelu((A*x) W1 + b1), split to bf16 hi/lo.
// ---------------------------------------------------------------------------
__global__ void __launch_bounds__(256)
gcn_partA(const float* __restrict__ x,
          const float* __restrict__ W1, const float* __restrict__ b1,
          int nTot) {
    __shared__ __align__(16) float s_x  [NJ * DIN];
    __shared__ __align__(16) float s_ax [NJ * DIN];
    __shared__ __align__(16) float s_h1 [NJ * HID];
    __shared__ __align__(16) float s_ah1[NJ * HID];
    __shared__ __align__(16) float s_W1 [DIN * HID];
    __shared__ __align__(16) float s_b1 [HID];
    __shared__ int s_off[NJ + 1];
    __shared__ int s_src[MAX_T];
    __shared__ __align__(16) float s_w[MAX_T];

    const int t = threadIdx.x;
    const int g = blockIdx.x;

    const float* xg = x + (size_t)g * (NJ * DIN);
    for (int i = t; i < NJ * DIN; i += 256) s_x[i] = xg[i];
    for (int i = t; i < DIN * HID; i += 256) s_W1[i] = W1[i];
    if (t < HID) s_b1[t] = b1[t];
    for (int i = t; i <= NJ; i += 256) s_off[i] = g_csr_off[i];
    for (int i = t; i < nTot; i += 256) { s_src[i] = g_csr_src[i]; s_w[i] = g_csr_w[i]; }
    __syncthreads();

    // phase 1: ax = A * x
    for (int idx = t; idx < NJ * DIN; idx += 256) {
        int j = idx / DIN, d = idx - j * DIN;
        float acc = 0.f;
        int e0 = s_off[j], e1 = s_off[j + 1];
        for (int e = e0; e < e1; e++) acc += s_w[e] * s_x[s_src[e] * DIN + d];
        s_ax[idx] = acc;
    }
    __syncthreads();

    // phase 2: h1 = gelu(ax @ W1 + b1)
    for (int idx = t; idx < NJ * HID; idx += 256) {
        int j = idx >> 6, k = idx & 63;
        float v = fmaf(s_ax[j * DIN + 0], s_W1[k],
                  fmaf(s_ax[j * DIN + 1], s_W1[HID + k],
                  fmaf(s_ax[j * DIN + 2], s_W1[2 * HID + k], s_b1[k])));
        s_h1[idx] = gelu_fast(v);
    }
    __syncthreads();

    // phase 3: ah1 = A * h1
    for (int idx = t; idx < NJ * HID; idx += 256) {
        int j = idx >> 6, k = idx & 63;
        float acc = 0.f;
        int e0 = s_off[j], e1 = s_off[j + 1];
        for (int e = e0; e < e1; e++) acc += s_w[e] * s_h1[(s_src[e] << 6) + k];
        s_ah1[idx] = acc;
    }
    __syncthreads();

    // split to bf16 hi/lo, coalesced store
    const size_t base = (size_t)g * (NJ * HID);
    for (int i = t; i < NJ * HID; i += 256) {
        float f = s_ah1[i];
        __nv_bfloat16 h = __float2bfloat16(f);
        __nv_bfloat16 l = __float2bfloat16(f - __bfloat162float(h));
        g_ah_hi[base + i] = h;
        g_ah_lo[base + i] = l;
    }
}

// ---------------------------------------------------------------------------
// Part B: out = gelu(AH1[Mtotal,64] @ W2[64,256] + b2) via warp-level
// bf16 mma.sync, 3-term hi/lo compensation. CTA tile = 128M x 128N
// (N-split halves SMEM to 74KB -> 2-3 CTAs/SM for latency hiding).
// grid.x encodes (m_tile, n_half): bid>>1 = m, bid&1 = n-half.
// ---------------------------------------------------------------------------
#define STRD 36
#define SM_AHI 0
#define SM_ALO (SM_AHI + 128 * STRD * 4)            // 18432
#define SM_BHI (SM_ALO + 128 * STRD * 4)            // 36864
#define SM_BLO (SM_BHI + 128 * STRD * 4)            // 55296
#define SM_B2  (SM_BLO + 128 * STRD * 4)            // 73728
#define SMB_TOTAL (SM_B2 + 128 * 4)                 // 74240

__global__ void __launch_bounds__(256)
gemm_gelu(const float* __restrict__ b2, float* __restrict__ out, int Mtotal) {
    extern __shared__ __align__(16) char smem[];
    uint32_t* sAh = (uint32_t*)(smem + SM_AHI);
    uint32_t* sAl = (uint32_t*)(smem + SM_ALO);
    uint32_t* sBh = (uint32_t*)(smem + SM_BHI);
    uint32_t* sBl = (uint32_t*)(smem + SM_BLO);
    float*    b2s = (float*)(smem + SM_B2);

    const int t   = threadIdx.x;
    const int wid = t >> 5;
    const int lid = t & 31;
    const int gq  = lid >> 2;
    const int tq  = lid & 3;
    const int mt  = blockIdx.x >> 1;        // m tile
    const int nh  = blockIdx.x & 1;         // n half (0 or 1)
    const long r0 = (long)mt * 128;
    const int  c0 = nh * 128;               // global column base of this half

    // ---- A tile: 128 rows x 32 u32 pairs (hi,lo); rows always in range ----
    for (int i = t; i < 128 * 32; i += 256) {
        int row = i >> 5, p = i & 31;
        long r = r0 + row; if (r >= Mtotal) r = Mtotal - 1;
        sAh[row * STRD + p] = ((const uint32_t*)g_ah_hi)[r * 32 + p];
        sAl[row * STRD + p] = ((const uint32_t*)g_ah_lo)[r * 32 + p];
    }
    // ---- B tile: this half's 128 W2^T rows ----
    for (int i = t; i < 128 * 32; i += 256) {
        int row = i >> 5, p = i & 31;
        sBh[row * STRD + p] = ((const uint32_t*)g_w2t_hi)[(c0 + row) * 32 + p];
        sBl[row * STRD + p] = ((const uint32_t*)g_w2t_lo)[(c0 + row) * 32 + p];
    }
    if (t < 128) b2s[t] = b2[c0 + t];
    __syncthreads();

    // ---- warp wid owns 16 local columns (2 N-tiles of 8) ----
    const int colbase = wid * 16;
    for (int m = 0; m < 8; m++) {
        float acc[2][4];
#pragma unroll
        for (int n = 0; n < 2; n++) { acc[n][0] = acc[n][1] = acc[n][2] = acc[n][3] = 0.f; }

#pragma unroll
        for (int q = 0; q < 4; q++) {
            const int ra = (m * 16 + gq) * STRD + q * 8 + tq;
            const uint32_t ah0 = sAh[ra],     ah1 = sAh[ra + 8 * STRD];
            const uint32_t ah2 = sAh[ra + 4], ah3 = sAh[ra + 8 * STRD + 4];
            const uint32_t al0 = sAl[ra],     al1 = sAl[ra + 8 * STRD];
            const uint32_t al2 = sAl[ra + 4], al3 = sAl[ra + 8 * STRD + 4];
#pragma unroll
            for (int n = 0; n < 2; n++) {
                const int rb = (colbase + n * 8 + gq) * STRD + q * 8 + tq;
                const uint32_t bh0 = sBh[rb], bh1 = sBh[rb + 4];
                const uint32_t bl0 = sBl[rb], bl1 = sBl[rb + 4];
                MMA_BF16(acc[n], ah0, ah1, ah2, ah3, bh0, bh1);
                MMA_BF16(acc[n], al0, al1, al2, al3, bh0, bh1);
                MMA_BF16(acc[n], ah0, ah1, ah2, ah3, bl0, bl1);
            }
        }

        const long ra0 = r0 + m * 16 + gq;
        const long ra1 = ra0 + 8;
        const bool v0 = (ra0 < Mtotal), v1 = (ra1 < Mtotal);
#pragma unroll
        for (int n = 0; n < 2; n++) {
            const int lc  = colbase + n * 8 + 2 * tq;       // local col
            const float bb0 = b2s[lc], bb1 = b2s[lc + 1];
            if (v0) {
                float2 o; o.x = gelu_fast(acc[n][0] + bb0);
                          o.y = gelu_fast(acc[n][1] + bb1);
                *(float2*)(out + ra0 * NOUT + c0 + lc) = o;
            }
            if (v1) {
                float2 o; o.x = gelu_fast(acc[n][2] + bb0);
                          o.y = gelu_fast(acc[n][3] + bb1);
                *(float2*)(out + ra1 * NOUT + c0 + lc) = o;
            }
        }
    }
}

// ---------------------------------------------------------------------------
extern "C" void kernel_launch(void* const* d_in, const int* in_sizes, int n_in,
                              void* d_out, int out_size) {
    const float* x  = (const float*)d_in[0];
    const void*  ei = d_in[1];                    // int32 or int64 (2,E)
    const float* W1 = (const float*)d_in[2];
    const float* b1 = (const float*)d_in[3];
    const float* W2 = (const float*)d_in[4];
    const float* b2 = (const float*)d_in[5];
    float* out = (float*)d_out;

    const int E  = in_sizes[1] / 2;               // 300
    const int nG = in_sizes[0] / (NJ * DIN);      // 2048
    const int nTot = E + NJ;                      // 375
    const int Mtotal = nG * NJ;                   // 153600
    const int tiles = (Mtotal + 127) / 128;       // 1200

    cudaFuncSetAttribute(gemm_gelu, cudaFuncAttributeMaxDynamicSharedMemorySize,
                         SMB_TOTAL);

    prep_w2<<<32, 512>>>(W2);
    setup_csr<<<1, 256>>>(ei, E);
    gcn_partA<<<nG, 256>>>(x, W1, b1, nTot);
    gemm_gelu<<<tiles * 2, 256, SMB_TOTAL>>>(b2, out, Mtotal);
}

// round 13
// speedup vs baseline: 1.0038x; 1.0038x over previous
#include <cuda_runtime.h>
#include <cuda_bf16.h>
#include <math.h>
#include <stdint.h>

// Problem constants: B=16,T=128 -> 2048 graphs; J=75; 3->64->256; E=300.
#define NJ    75
#define DIN   3
#define HID   64
#define NOUT  256
#define MAX_E 1024
#define MAX_T 544
#define MAXG  2048

// ---------------- persistent device scratch ----------------
__device__ int   g_csr_src[MAX_T];
__device__ float g_csr_w[MAX_T];
__device__ int   g_csr_off[NJ + 1];
__device__ __nv_bfloat16 g_ah_hi[MAXG * NJ * HID];   // ah1 split hi [row][k]
__device__ __nv_bfloat16 g_ah_lo[MAXG * NJ * HID];   // ah1 split lo
__device__ __nv_bfloat16 g_w2t_hi[NOUT * HID];       // W2^T split hi [n][k]
__device__ __nv_bfloat16 g_w2t_lo[NOUT * HID];       // W2^T split lo

// ---------------- math helpers ----------------
__device__ __forceinline__ float gelu_fast(float v) {
    const float x  = v * 0.70710678118654752f;
    const float ax = fabsf(x);
    const float den = fmaf(0.3275911f, ax, 1.0f);
    const float t   = __frcp_rn(den);
    float p = fmaf(1.061405429f, t, -1.453152027f);
    p = fmaf(p, t, 1.421413741f);
    p = fmaf(p, t, -0.284496736f);
    p = fmaf(p, t, 0.254829592f);
    p = p * t;
    const float ex   = __expf(-x * x);
    const float erfa = fmaf(-p, ex, 1.0f);
    return 0.5f * v * (1.0f + copysignf(erfa, x));
}
__device__ __forceinline__ int clampj(int v) {
    return v < 0 ? 0 : (v >= NJ ? NJ - 1 : v);
}
__device__ __forceinline__ uint32_t smem_u32(const void* p) {
    uint32_t a;
    asm("{ .reg .u64 t; cvta.to.shared.u64 t, %1; cvt.u32.u64 %0, t; }"
        : "=r"(a) : "l"(p));
    return a;
}

// Classic warp-level bf16 MMA (sm_80+ PTX, legal on plain sm_103 target).
#define MMA_BF16(d, a0, a1, a2, a3, b0, b1)                                   \
    asm volatile("mma.sync.aligned.m16n8k16.row.col.f32.bf16.bf16.f32 "       \
        "{%0,%1,%2,%3}, {%4,%5,%6,%7}, {%8,%9}, {%0,%1,%2,%3};"               \
        : "+f"((d)[0]), "+f"((d)[1]), "+f"((d)[2]), "+f"((d)[3])              \
        : "r"(a0), "r"(a1), "r"(a2), "r"(a3), "r"(b0), "r"(b1))

// ldmatrix: 4x (8x8 b16) tiles -> 4 regs in mma fragment layout (sm_75+ PTX).
#define LDSM_X4(r0, r1, r2, r3, addr)                                         \
    asm volatile("ldmatrix.sync.aligned.m8n8.x4.shared.b16 {%0,%1,%2,%3}, [%4];" \
        : "=r"(r0), "=r"(r1), "=r"(r2), "=r"(r3) : "r"(addr))

// ---------------------------------------------------------------------------
// W2^T bf16 hi/lo split — multi-block.
// ---------------------------------------------------------------------------
__global__ void prep_w2(const float* __restrict__ W2) {
    int i = blockIdx.x * blockDim.x + threadIdx.x;
    if (i < NOUT * HID) {
        int n = i >> 6, k = i & 63;
        float f = W2[k * NOUT + n];
        __nv_bfloat16 h = __float2bfloat16(f);
        __nv_bfloat16 l = __float2bfloat16(f - __bfloat162float(h));
        g_w2t_hi[i] = h;
        g_w2t_lo[i] = l;
    }
}

// ---------------------------------------------------------------------------
// CSR of normalized adjacency. One block (small).
// ---------------------------------------------------------------------------
__global__ void __launch_bounds__(256)
setup_csr(const void* __restrict__ eiv, int E) {
    const int*       e32 = (const int*)eiv;
    const long long* e64 = (const long long*)eiv;

    __shared__ int   s_odd;
    __shared__ int   s_src[MAX_E];
    __shared__ int   s_dst[MAX_E];
    __shared__ int   s_deg[NJ];
    __shared__ float s_dis[NJ];
    __shared__ int   s_off[NJ + 1];

    const int t = threadIdx.x;

    if (t == 0) s_odd = 0;
    __syncthreads();
    {
        int local = 0;
        for (int i = 2 * t + 1; i < 2 * E; i += 2 * blockDim.x)
            local |= (e32[i] != 0);
        if (local) atomicOr(&s_odd, 1);
    }
    __syncthreads();
    const int is64 = !s_odd;

    for (int i = t; i < E; i += blockDim.x) {
        int sv, dv;
        if (is64) { sv = (int)e64[i]; dv = (int)e64[E + i]; }
        else      { sv = e32[i];      dv = e32[E + i]; }
        s_src[i] = clampj(sv);
        s_dst[i] = clampj(dv);
    }
    for (int j = t; j < NJ; j += blockDim.x) s_deg[j] = 1;  // self loop
    __syncthreads();
    for (int i = t; i < E; i += blockDim.x) atomicAdd(&s_deg[s_dst[i]], 1);
    __syncthreads();
    if (t == 0) {
        int acc = 0;
        for (int j = 0; j < NJ; j++) { s_off[j] = acc; acc += s_deg[j]; }
        s_off[NJ] = acc;
    }
    for (int j = t; j < NJ; j += blockDim.x) s_dis[j] = rsqrtf((float)s_deg[j]);
    __syncthreads();
    if (t < NJ) {
        int p = s_off[t];
        float dj = s_dis[t];
        for (int e = 0; e < E; e++) {
            if (s_dst[e] == t) {
                int se = s_src[e];
                g_csr_src[p] = se;
                g_csr_w[p]   = s_dis[se] * dj;
                p++;
            }
        }
        g_csr_src[p] = t;               // self loop last (reference order)
        g_csr_w[p]   = dj * dj;
    }
    for (int j = t; j <= NJ; j += blockDim.x) g_csr_off[j] = s_off[j];
}

// ---------------------------------------------------------------------------
// Part A (per-graph CTA): ah1 = A * gelu((A*x) W1 + b1), split to bf16 hi/lo.
// ---------------------------------------------------------------------------
__global__ void __launch_bounds__(256)
gcn_partA(const float* __restrict__ x,
          const float* __restrict__ W1, const float* __restrict__ b1,
          int nTot) {
    __shared__ __align__(16) float s_x  [NJ * DIN];
    __shared__ __align__(16) float s_ax [NJ * DIN];
    __shared__ __align__(16) float s_h1 [NJ * HID];
    __shared__ __align__(16) float s_ah1[NJ * HID];
    __shared__ __align__(16) float s_W1 [DIN * HID];
    __shared__ __align__(16) float s_b1 [HID];
    __shared__ int s_off[NJ + 1];
    __shared__ int s_src[MAX_T];
    __shared__ __align__(16) float s_w[MAX_T];

    const int t = threadIdx.x;
    const int g = blockIdx.x;

    const float* xg = x + (size_t)g * (NJ * DIN);
    for (int i = t; i < NJ * DIN; i += 256) s_x[i] = xg[i];
    for (int i = t; i < DIN * HID; i += 256) s_W1[i] = W1[i];
    if (t < HID) s_b1[t] = b1[t];
    for (int i = t; i <= NJ; i += 256) s_off[i] = g_csr_off[i];
    for (int i = t; i < nTot; i += 256) { s_src[i] = g_csr_src[i]; s_w[i] = g_csr_w[i]; }
    __syncthreads();

    for (int idx = t; idx < NJ * DIN; idx += 256) {
        int j = idx / DIN, d = idx - j * DIN;
        float acc = 0.f;
        int e0 = s_off[j], e1 = s_off[j + 1];
        for (int e = e0; e < e1; e++) acc += s_w[e] * s_x[s_src[e] * DIN + d];
        s_ax[idx] = acc;
    }
    __syncthreads();

    for (int idx = t; idx < NJ * HID; idx += 256) {
        int j = idx >> 6, k = idx & 63;
        float v = fmaf(s_ax[j * DIN + 0], s_W1[k],
                  fmaf(s_ax[j * DIN + 1], s_W1[HID + k],
                  fmaf(s_ax[j * DIN + 2], s_W1[2 * HID + k], s_b1[k])));
        s_h1[idx] = gelu_fast(v);
    }
    __syncthreads();

    for (int idx = t; idx < NJ * HID; idx += 256) {
        int j = idx >> 6, k = idx & 63;
        float acc = 0.f;
        int e0 = s_off[j], e1 = s_off[j + 1];
        for (int e = e0; e < e1; e++) acc += s_w[e] * s_h1[(s_src[e] << 6) + k];
        s_ah1[idx] = acc;
    }
    __syncthreads();

    const size_t base = (size_t)g * (NJ * HID);
    for (int i = t; i < NJ * HID; i += 256) {
        float f = s_ah1[i];
        __nv_bfloat16 h = __float2bfloat16(f);
        __nv_bfloat16 l = __float2bfloat16(f - __bfloat162float(h));
        g_ah_hi[base + i] = h;
        g_ah_lo[base + i] = l;
    }
}

// ---------------------------------------------------------------------------
// Part B: out = gelu(AH1[Mtotal,64] @ W2[64,256] + b2), warp mma.sync,
// 3-term hi/lo compensation. CTA tile = 128M x 128N.
// Fragment loads via ldmatrix.x4 (4x fewer LDS instructions); B fragments
// are m-invariant and hoisted into registers before the m-loop.
// ---------------------------------------------------------------------------
#define STRD 36
#define SM_AHI 0
#define SM_ALO (SM_AHI + 128 * STRD * 4)            // 18432
#define SM_BHI (SM_ALO + 128 * STRD * 4)            // 36864
#define SM_BLO (SM_BHI + 128 * STRD * 4)            // 55296
#define SM_B2  (SM_BLO + 128 * STRD * 4)            // 73728
#define SMB_TOTAL (SM_B2 + 128 * 4)                 // 74240

__global__ void __launch_bounds__(256)
gemm_gelu(const float* __restrict__ b2, float* __restrict__ out, int Mtotal) {
    extern __shared__ __align__(16) char smem[];
    uint32_t* sAh = (uint32_t*)(smem + SM_AHI);
    uint32_t* sAl = (uint32_t*)(smem + SM_ALO);
    uint32_t* sBh = (uint32_t*)(smem + SM_BHI);
    uint32_t* sBl = (uint32_t*)(smem + SM_BLO);
    float*    b2s = (float*)(smem + SM_B2);

    const int t   = threadIdx.x;
    const int wid = t >> 5;
    const int lid = t & 31;
    const int gq  = lid >> 2;
    const int tq  = lid & 3;
    const int mt  = blockIdx.x >> 1;        // m tile
    const int nh  = blockIdx.x & 1;         // n half
    const long r0 = (long)mt * 128;
    const int  c0 = nh * 128;

    // ---- cooperative tile loads (global -> smem), rows in-range by design ----
    for (int i = t; i < 128 * 32; i += 256) {
        int row = i >> 5, p = i & 31;
        long r = r0 + row; if (r >= Mtotal) r = Mtotal - 1;
        sAh[row * STRD + p] = ((const uint32_t*)g_ah_hi)[r * 32 + p];
        sAl[row * STRD + p] = ((const uint32_t*)g_ah_lo)[r * 32 + p];
    }
    for (int i = t; i < 128 * 32; i += 256) {
        int row = i >> 5, p = i & 31;
        sBh[row * STRD + p] = ((const uint32_t*)g_w2t_hi)[(c0 + row) * 32 + p];
        sBl[row * STRD + p] = ((const uint32_t*)g_w2t_lo)[(c0 + row) * 32 + p];
    }
    if (t < 128) b2s[t] = b2[c0 + t];
    __syncthreads();

    // ---- per-lane ldmatrix row offset (x4 layout):
    // lanes 0-7 -> mat0 rows, 8-15 -> mat1 (+8 rows), 16-23 -> mat2 (+8 k),
    // 24-31 -> mat3 (+8 rows, +8 k). Banks: row*36 % 32 = 4*row -> conflict-free.
    const uint32_t frag_row = (lid & 7) + ((lid >> 3) & 1) * 8;
    const uint32_t frag_k   = (lid >> 4) * 4;       // u32 offset (+8 bf16)
    const uint32_t frag_off = (frag_row * STRD + frag_k) * 4;   // bytes

    const uint32_t sb = smem_u32(smem);
    const int colbase = wid * 16;                   // 16 local N columns/warp

    // ---- hoist B fragments (m-invariant): 4 q-steps x {b0n0,b0n1,b1n0,b1n1} ----
    uint32_t bh[4][4], bl[4][4];
    {
        const uint32_t bbase_h = sb + SM_BHI + colbase * STRD * 4 + frag_off;
        const uint32_t bbase_l = sb + SM_BLO + colbase * STRD * 4 + frag_off;
#pragma unroll
        for (int q = 0; q < 4; q++) {
            LDSM_X4(bh[q][0], bh[q][1], bh[q][2], bh[q][3], bbase_h + q * 32);
            LDSM_X4(bl[q][0], bl[q][1], bl[q][2], bl[q][3], bbase_l + q * 32);
        }
    }

    const uint32_t abase_h = sb + SM_AHI + frag_off;
    const uint32_t abase_l = sb + SM_ALO + frag_off;

    for (int m = 0; m < 8; m++) {
        float acc[2][4];
#pragma unroll
        for (int n = 0; n < 2; n++) { acc[n][0] = acc[n][1] = acc[n][2] = acc[n][3] = 0.f; }

        const uint32_t am = m * 16 * STRD * 4;
#pragma unroll
        for (int q = 0; q < 4; q++) {
            uint32_t ah0, ah1, ah2, ah3, al0, al1, al2, al3;
            LDSM_X4(ah0, ah1, ah2, ah3, abase_h + am + q * 32);
            LDSM_X4(al0, al1, al2, al3, abase_l + am + q * 32);
#pragma unroll
            for (int n = 0; n < 2; n++) {
                MMA_BF16(acc[n], ah0, ah1, ah2, ah3, bh[q][n], bh[q][2 + n]);
                MMA_BF16(acc[n], al0, al1, al2, al3, bh[q][n], bh[q][2 + n]);
                MMA_BF16(acc[n], ah0, ah1, ah2, ah3, bl[q][n], bl[q][2 + n]);
            }
        }

        const long ra0 = r0 + m * 16 + gq;
        const long ra1 = ra0 + 8;
        const bool v0 = (ra0 < Mtotal), v1 = (ra1 < Mtotal);
#pragma unroll
        for (int n = 0; n < 2; n++) {
            const int lc  = colbase + n * 8 + 2 * tq;
            const float bb0 = b2s[lc], bb1 = b2s[lc + 1];
            if (v0) {
                float2 o; o.x = gelu_fast(acc[n][0] + bb0);
                          o.y = gelu_fast(acc[n][1] + bb1);
                *(float2*)(out + ra0 * NOUT + c0 + lc) = o;
            }
            if (v1) {
                float2 o; o.x = gelu_fast(acc[n][2] + bb0);
                          o.y = gelu_fast(acc[n][3] + bb1);
                *(float2*)(out + ra1 * NOUT + c0 + lc) = o;
            }
        }
    }
}

// ---------------------------------------------------------------------------
extern "C" void kernel_launch(void* const* d_in, const int* in_sizes, int n_in,
                              void* d_out, int out_size) {
    const float* x  = (const float*)d_in[0];
    const void*  ei = d_in[1];                    // int32 or int64 (2,E)
    const float* W1 = (const float*)d_in[2];
    const float* b1 = (const float*)d_in[3];
    const float* W2 = (const float*)d_in[4];
    const float* b2 = (const float*)d_in[5];
    float* out = (float*)d_out;

    const int E  = in_sizes[1] / 2;               // 300
    const int nG = in_sizes[0] / (NJ * DIN);      // 2048
    const int nTot = E + NJ;                      // 375
    const int Mtotal = nG * NJ;                   // 153600
    const int tiles = (Mtotal + 127) / 128;       // 1200

    cudaFuncSetAttribute(gemm_gelu, cudaFuncAttributeMaxDynamicSharedMemorySize,
                         SMB_TOTAL);

    prep_w2<<<32, 512>>>(W2);
    setup_csr<<<1, 256>>>(ei, E);
    gcn_partA<<<nG, 256>>>(x, W1, b1, nTot);
    gemm_gelu<<<tiles * 2, 256, SMB_TOTAL>>>(b2, out, Mtotal);
}

// round 14
// speedup vs baseline: 1.3313x; 1.3264x over previous
#include <cuda_runtime.h>
#include <cuda_bf16.h>
#include <math.h>
#include <stdint.h>

// Problem constants: B=16,T=128 -> 2048 graphs; J=75; 3->64->256; E=300.
#define NJ    75
#define DIN   3
#define HID   64
#define NOUT  256
#define MAX_E 1024
#define MAX_T 544
#define MAXG  2048
#define TPC   8        // m-tiles per CTA in gemm_gelu

// ---------------- persistent device scratch ----------------
__device__ int   g_csr_src[MAX_T];
__device__ float g_csr_w[MAX_T];
__device__ int   g_csr_off[NJ + 1];
__device__ __nv_bfloat16 g_ah_hi[MAXG * NJ * HID];   // ah1 split hi [row][k]
__device__ __nv_bfloat16 g_ah_lo[MAXG * NJ * HID];   // ah1 split lo
__device__ __nv_bfloat16 g_w2t_hi[NOUT * HID];       // W2^T split hi [n][k]
__device__ __nv_bfloat16 g_w2t_lo[NOUT * HID];       // W2^T split lo

// ---------------- math helpers ----------------
__device__ __forceinline__ float gelu_fast(float v) {
    const float x  = v * 0.70710678118654752f;
    const float ax = fabsf(x);
    const float den = fmaf(0.3275911f, ax, 1.0f);
    const float t   = __frcp_rn(den);
    float p = fmaf(1.061405429f, t, -1.453152027f);
    p = fmaf(p, t, 1.421413741f);
    p = fmaf(p, t, -0.284496736f);
    p = fmaf(p, t, 0.254829592f);
    p = p * t;
    const float ex   = __expf(-x * x);
    const float erfa = fmaf(-p, ex, 1.0f);
    return 0.5f * v * (1.0f + copysignf(erfa, x));
}
__device__ __forceinline__ int clampj(int v) {
    return v < 0 ? 0 : (v >= NJ ? NJ - 1 : v);
}
__device__ __forceinline__ uint32_t smem_u32(const void* p) {
    uint32_t a;
    asm("{ .reg .u64 t; cvta.to.shared.u64 t, %1; cvt.u32.u64 %0, t; }"
        : "=r"(a) : "l"(p));
    return a;
}

// Warp-level bf16 MMA + ldmatrix + cp.async (all sm_80/75 PTX, legal on sm_103).
#define MMA_BF16(d, a0, a1, a2, a3, b0, b1)                                   \
    asm volatile("mma.sync.aligned.m16n8k16.row.col.f32.bf16.bf16.f32 "       \
        "{%0,%1,%2,%3}, {%4,%5,%6,%7}, {%8,%9}, {%0,%1,%2,%3};"               \
        : "+f"((d)[0]), "+f"((d)[1]), "+f"((d)[2]), "+f"((d)[3])              \
        : "r"(a0), "r"(a1), "r"(a2), "r"(a3), "r"(b0), "r"(b1))

#define LDSM_X4(r0, r1, r2, r3, addr)                                         \
    asm volatile("ldmatrix.sync.aligned.m8n8.x4.shared.b16 {%0,%1,%2,%3}, [%4];" \
        : "=r"(r0), "=r"(r1), "=r"(r2), "=r"(r3) : "r"(addr))

#define CP_ASYNC16(dst, src)                                                  \
    asm volatile("cp.async.ca.shared.global [%0], [%1], 16;"                  \
        :: "r"(dst), "l"(src) : "memory")
#define CP_COMMIT()  asm volatile("cp.async.commit_group;" ::: "memory")
#define CP_WAIT0()   asm volatile("cp.async.wait_group 0;" ::: "memory")

// ---------------------------------------------------------------------------
// W2^T bf16 hi/lo split — multi-block.
// ---------------------------------------------------------------------------
__global__ void prep_w2(const float* __restrict__ W2) {
    int i = blockIdx.x * blockDim.x + threadIdx.x;
    if (i < NOUT * HID) {
        int n = i >> 6, k = i & 63;
        float f = W2[k * NOUT + n];
        __nv_bfloat16 h = __float2bfloat16(f);
        __nv_bfloat16 l = __float2bfloat16(f - __bfloat162float(h));
        g_w2t_hi[i] = h;
        g_w2t_lo[i] = l;
    }
}

// ---------------------------------------------------------------------------
// CSR of normalized adjacency. One block (small).
// ---------------------------------------------------------------------------
__global__ void __launch_bounds__(256)
setup_csr(const void* __restrict__ eiv, int E) {
    const int*       e32 = (const int*)eiv;
    const long long* e64 = (const long long*)eiv;

    __shared__ int   s_odd;
    __shared__ int   s_src[MAX_E];
    __shared__ int   s_dst[MAX_E];
    __shared__ int   s_deg[NJ];
    __shared__ float s_dis[NJ];
    __shared__ int   s_off[NJ + 1];

    const int t = threadIdx.x;

    if (t == 0) s_odd = 0;
    __syncthreads();
    {
        int local = 0;
        for (int i = 2 * t + 1; i < 2 * E; i += 2 * blockDim.x)
            local |= (e32[i] != 0);
        if (local) atomicOr(&s_odd, 1);
    }
    __syncthreads();
    const int is64 = !s_odd;

    for (int i = t; i < E; i += blockDim.x) {
        int sv, dv;
        if (is64) { sv = (int)e64[i]; dv = (int)e64[E + i]; }
        else      { sv = e32[i];      dv = e32[E + i]; }
        s_src[i] = clampj(sv);
        s_dst[i] = clampj(dv);
    }
    for (int j = t; j < NJ; j += blockDim.x) s_deg[j] = 1;  // self loop
    __syncthreads();
    for (int i = t; i < E; i += blockDim.x) atomicAdd(&s_deg[s_dst[i]], 1);
    __syncthreads();
    if (t == 0) {
        int acc = 0;
        for (int j = 0; j < NJ; j++) { s_off[j] = acc; acc += s_deg[j]; }
        s_off[NJ] = acc;
    }
    for (int j = t; j < NJ; j += blockDim.x) s_dis[j] = rsqrtf((float)s_deg[j]);
    __syncthreads();
    if (t < NJ) {
        int p = s_off[t];
        float dj = s_dis[t];
        for (int e = 0; e < E; e++) {
            if (s_dst[e] == t) {
                int se = s_src[e];
                g_csr_src[p] = se;
                g_csr_w[p]   = s_dis[se] * dj;
                p++;
            }
        }
        g_csr_src[p] = t;               // self loop last (reference order)
        g_csr_w[p]   = dj * dj;
    }
    for (int j = t; j <= NJ; j += blockDim.x) g_csr_off[j] = s_off[j];
}

// ---------------------------------------------------------------------------
// Part A (per-graph CTA): ah1 = A * gelu((A*x) W1 + b1), split to bf16 hi/lo.
// ---------------------------------------------------------------------------
__global__ void __launch_bounds__(256)
gcn_partA(const float* __restrict__ x,
          const float* __restrict__ W1, const float* __restrict__ b1,
          int nTot) {
    __shared__ __align__(16) float s_x  [NJ * DIN];
    __shared__ __align__(16) float s_ax [NJ * DIN];
    __shared__ __align__(16) float s_h1 [NJ * HID];
    __shared__ __align__(16) float s_ah1[NJ * HID];
    __shared__ __align__(16) float s_W1 [DIN * HID];
    __shared__ __align__(16) float s_b1 [HID];
    __shared__ int s_off[NJ + 1];
    __shared__ int s_src[MAX_T];
    __shared__ __align__(16) float s_w[MAX_T];

    const int t = threadIdx.x;
    const int g = blockIdx.x;

    const float* xg = x + (size_t)g * (NJ * DIN);
    for (int i = t; i < NJ * DIN; i += 256) s_x[i] = xg[i];
    for (int i = t; i < DIN * HID; i += 256) s_W1[i] = W1[i];
    if (t < HID) s_b1[t] = b1[t];
    for (int i = t; i <= NJ; i += 256) s_off[i] = g_csr_off[i];
    for (int i = t; i < nTot; i += 256) { s_src[i] = g_csr_src[i]; s_w[i] = g_csr_w[i]; }
    __syncthreads();

    for (int idx = t; idx < NJ * DIN; idx += 256) {
        int j = idx / DIN, d = idx - j * DIN;
        float acc = 0.f;
        int e0 = s_off[j], e1 = s_off[j + 1];
        for (int e = e0; e < e1; e++) acc += s_w[e] * s_x[s_src[e] * DIN + d];
        s_ax[idx] = acc;
    }
    __syncthreads();

    for (int idx = t; idx < NJ * HID; idx += 256) {
        int j = idx >> 6, k = idx & 63;
        float v = fmaf(s_ax[j * DIN + 0], s_W1[k],
                  fmaf(s_ax[j * DIN + 1], s_W1[HID + k],
                  fmaf(s_ax[j * DIN + 2], s_W1[2 * HID + k], s_b1[k])));
        s_h1[idx] = gelu_fast(v);
    }
    __syncthreads();

    for (int idx = t; idx < NJ * HID; idx += 256) {
        int j = idx >> 6, k = idx & 63;
        float acc = 0.f;
        int e0 = s_off[j], e1 = s_off[j + 1];
        for (int e = e0; e < e1; e++) acc += s_w[e] * s_h1[(s_src[e] << 6) + k];
        s_ah1[idx] = acc;
    }
    __syncthreads();

    const size_t base = (size_t)g * (NJ * HID);
    for (int i = t; i < NJ * HID; i += 256) {
        float f = s_ah1[i];
        __nv_bfloat16 h = __float2bfloat16(f);
        __nv_bfloat16 l = __float2bfloat16(f - __bfloat162float(h));
        g_ah_hi[base + i] = h;
        g_ah_lo[base + i] = l;
    }
}

// ---------------------------------------------------------------------------
// Part B: out = gelu(AH1 @ W2 + b2), warp mma.sync, 3-term hi/lo comp.
// Persistent-ish CTAs: each owns TPC=8 consecutive 128-row m-tiles for one
// 128-col n-half. B (W2^T half) loaded ONCE per CTA; A tiles double-buffered
// via cp.async so tile t+1 streams while tile t computes.
// Layout: u32 rows at STRD=36 -> conflict-free ldmatrix.
// ---------------------------------------------------------------------------
#define STRD   36
#define TILE_U32S (128 * 32)                        // u32 per (hi or lo) tile
#define TILE_BYTES (128 * STRD * 4)                 // padded tile in smem: 18432
#define SM_BHI 0
#define SM_BLO (SM_BHI + TILE_BYTES)                // 18432
#define SM_A0  (SM_BLO + TILE_BYTES)                // 36864 (stage0: hi,lo)
#define SM_A1  (SM_A0 + 2 * TILE_BYTES)             // 73728 (stage1: hi,lo)
#define SM_B2  (SM_A1 + 2 * TILE_BYTES)             // 110592
#define SMB_TOTAL (SM_B2 + 128 * 4)                 // 111104

// async-copy one (hi,lo) A tile pair into a stage. 8x cp.async/thread.
__device__ __forceinline__ void prefetch_A(uint32_t sb_stage, long r0, int t) {
    // 1024 16B-chunks per array; thread t takes chunks {t, t+256, t+512, t+768}
#pragma unroll
    for (int i = 0; i < 4; i++) {
        int c = t + 256 * i;
        int row = c >> 3, seg = c & 7;
        uint32_t dst = sb_stage + row * (STRD * 4) + seg * 16;
        CP_ASYNC16(dst, (const char*)(g_ah_hi + (r0 + row) * HID + seg * 8));
        CP_ASYNC16(dst + 2 * TILE_BYTES == 0 ? dst : dst + TILE_BYTES,  // lo at +TILE_BYTES
                   (const char*)(g_ah_lo + (r0 + row) * HID + seg * 8));
    }
}

__global__ void __launch_bounds__(256)
gemm_gelu(const float* __restrict__ b2, float* __restrict__ out, int Mtotal) {
    extern __shared__ __align__(16) char smem[];
    float* b2s = (float*)(smem + SM_B2);

    const int t   = threadIdx.x;
    const int wid = t >> 5;
    const int lid = t & 31;
    const int gq  = lid >> 2;
    const int tq  = lid & 3;
    const int blk = blockIdx.x >> 1;        // m-block (TPC tiles each)
    const int nh  = blockIdx.x & 1;         // n half
    const int c0  = nh * 128;
    const long mt0 = (long)blk * TPC;       // first m-tile

    const uint32_t sb = smem_u32(smem);

    // ---- B tile (once) + A tile 0, all via cp.async ----
#pragma unroll
    for (int i = 0; i < 4; i++) {
        int c = t + 256 * i;
        int row = c >> 3, seg = c & 7;
        uint32_t dst = sb + SM_BHI + row * (STRD * 4) + seg * 16;
        CP_ASYNC16(dst, (const char*)(g_w2t_hi + (c0 + row) * HID + seg * 8));
        CP_ASYNC16(dst + TILE_BYTES, (const char*)(g_w2t_lo + (c0 + row) * HID + seg * 8));
    }
    prefetch_A(sb + SM_A0, mt0 * 128, t);
    CP_COMMIT();
    if (t < 128) b2s[t] = b2[c0 + t];
    CP_WAIT0();
    __syncthreads();

    // ---- per-lane ldmatrix offset (x4): conflict-free with STRD=36 ----
    const uint32_t frag_row = (lid & 7) + ((lid >> 3) & 1) * 8;
    const uint32_t frag_k   = (lid >> 4) * 4;
    const uint32_t frag_off = (frag_row * STRD + frag_k) * 4;

    const int colbase = wid * 16;

    // ---- hoist B fragments (CTA-invariant) ----
    uint32_t bh[4][4], bl[4][4];
    {
        const uint32_t bb_h = sb + SM_BHI + colbase * STRD * 4 + frag_off;
        const uint32_t bb_l = sb + SM_BLO + colbase * STRD * 4 + frag_off;
#pragma unroll
        for (int q = 0; q < 4; q++) {
            LDSM_X4(bh[q][0], bh[q][1], bh[q][2], bh[q][3], bb_h + q * 32);
            LDSM_X4(bl[q][0], bl[q][1], bl[q][2], bl[q][3], bb_l + q * 32);
        }
    }

    for (int it = 0; it < TPC; it++) {
        // prefetch next A tile into the other stage (overlaps compute below)
        if (it + 1 < TPC) {
            uint32_t stage = sb + ((it + 1) & 1 ? SM_A1 : SM_A0);
            prefetch_A(stage, (mt0 + it + 1) * 128, t);
            CP_COMMIT();
        }

        const uint32_t abase = sb + ((it & 1) ? SM_A1 : SM_A0) + frag_off;
        const long r0 = (mt0 + it) * 128;

        for (int m = 0; m < 8; m++) {
            // split accumulators: hi-chain (depth 8) + lo-chain (depth 4)
            float acch[2][4], accl[2][4];
#pragma unroll
            for (int n = 0; n < 2; n++)
#pragma unroll
                for (int v = 0; v < 4; v++) { acch[n][v] = 0.f; accl[n][v] = 0.f; }

            const uint32_t am = m * 16 * STRD * 4;
#pragma unroll
            for (int q = 0; q < 4; q++) {
                uint32_t ah0, ah1, ah2, ah3, al0, al1, al2, al3;
                LDSM_X4(ah0, ah1, ah2, ah3, abase + am + q * 32);
                LDSM_X4(al0, al1, al2, al3, abase + TILE_BYTES + am + q * 32);
#pragma unroll
                for (int n = 0; n < 2; n++) {
                    MMA_BF16(acch[n], ah0, ah1, ah2, ah3, bh[q][n], bh[q][2 + n]);
                    MMA_BF16(acch[n], al0, al1, al2, al3, bh[q][n], bh[q][2 + n]);
                    MMA_BF16(accl[n], ah0, ah1, ah2, ah3, bl[q][n], bl[q][2 + n]);
                }
            }

            const long ra0 = r0 + m * 16 + gq;
            const long ra1 = ra0 + 8;
#pragma unroll
            for (int n = 0; n < 2; n++) {
                const int lc = colbase + n * 8 + 2 * tq;
                const float bb0 = b2s[lc], bb1 = b2s[lc + 1];
                float2 o0, o1;
                o0.x = gelu_fast(acch[n][0] + accl[n][0] + bb0);
                o0.y = gelu_fast(acch[n][1] + accl[n][1] + bb1);
                o1.x = gelu_fast(acch[n][2] + accl[n][2] + bb0);
                o1.y = gelu_fast(acch[n][3] + accl[n][3] + bb1);
                *(float2*)(out + ra0 * NOUT + c0 + lc) = o0;
                *(float2*)(out + ra1 * NOUT + c0 + lc) = o1;
            }
        }

        if (it + 1 < TPC) { CP_WAIT0(); __syncthreads(); }
    }
}

// ---------------------------------------------------------------------------
extern "C" void kernel_launch(void* const* d_in, const int* in_sizes, int n_in,
                              void* d_out, int out_size) {
    const float* x  = (const float*)d_in[0];
    const void*  ei = d_in[1];                    // int32 or int64 (2,E)
    const float* W1 = (const float*)d_in[2];
    const float* b1 = (const float*)d_in[3];
    const float* W2 = (const float*)d_in[4];
    const float* b2 = (const float*)d_in[5];
    float* out = (float*)d_out;

    const int E  = in_sizes[1] / 2;               // 300
    const int nG = in_sizes[0] / (NJ * DIN);      // 2048
    const int nTot = E + NJ;                      // 375
    const int Mtotal = nG * NJ;                   // 153600
    const int tiles = Mtotal / 128;               // 1200 (exact)
    const int blocks = (tiles / TPC) * 2;         // 300

    cudaFuncSetAttribute(gemm_gelu, cudaFuncAttributeMaxDynamicSharedMemorySize,
                         SMB_TOTAL);

    prep_w2<<<32, 512>>>(W2);
    setup_csr<<<1, 256>>>(ei, E);
    gcn_partA<<<nG, 256>>>(x, W1, b1, nTot);
    gemm_gelu<<<blocks, 256, SMB_TOTAL>>>(b2, out, Mtotal);
}

// round 15
// speedup vs baseline: 1.4677x; 1.1024x over previous
#include <cuda_runtime.h>
#include <cuda_bf16.h>
#include <math.h>
#include <stdint.h>

// Problem constants: B=16,T=128 -> 2048 graphs; J=75; 3->64->256; E=300.
#define NJ    75
#define DIN   3
#define HID   64
#define NOUT  256
#define MAX_E 1024
#define MAX_T 544
#define MAXG  2048
#define TPC   8        // m-tiles per CTA in gemm_gelu

// ---------------- persistent device scratch ----------------
__device__ int   g_csr_src[MAX_T];
__device__ float g_csr_w[MAX_T];
__device__ int   g_csr_off[NJ + 1];
__device__ __nv_bfloat16 g_ah_hi[MAXG * NJ * HID];   // ah1 split hi [row][k]
__device__ __nv_bfloat16 g_ah_lo[MAXG * NJ * HID];   // ah1 split lo
__device__ __nv_bfloat16 g_w2t_hi[NOUT * HID];       // W2^T split hi [n][k]
__device__ __nv_bfloat16 g_w2t_lo[NOUT * HID];       // W2^T split lo

// ---------------- math helpers ----------------
// Branchless gelu; rcp.approx (1 MUFU) is ample for the poly argument.
__device__ __forceinline__ float gelu_fast(float v) {
    const float x  = v * 0.70710678118654752f;
    const float ax = fabsf(x);
    const float den = fmaf(0.3275911f, ax, 1.0f);
    float t;
    asm("rcp.approx.f32 %0, %1;" : "=f"(t) : "f"(den));
    float p = fmaf(1.061405429f, t, -1.453152027f);
    p = fmaf(p, t, 1.421413741f);
    p = fmaf(p, t, -0.284496736f);
    p = fmaf(p, t, 0.254829592f);
    p = p * t;
    const float ex   = __expf(-x * x);
    const float erfa = fmaf(-p, ex, 1.0f);
    return 0.5f * v * (1.0f + copysignf(erfa, x));
}
__device__ __forceinline__ int clampj(int v) {
    return v < 0 ? 0 : (v >= NJ ? NJ - 1 : v);
}
__device__ __forceinline__ uint32_t smem_u32(const void* p) {
    uint32_t a;
    asm("{ .reg .u64 t; cvta.to.shared.u64 t, %1; cvt.u32.u64 %0, t; }"
        : "=r"(a) : "l"(p));
    return a;
}

// Warp-level bf16 MMA + ldmatrix + cp.async (sm_80/75 PTX, legal on sm_103).
#define MMA_BF16(d, a0, a1, a2, a3, b0, b1)                                   \
    asm volatile("mma.sync.aligned.m16n8k16.row.col.f32.bf16.bf16.f32 "       \
        "{%0,%1,%2,%3}, {%4,%5,%6,%7}, {%8,%9}, {%0,%1,%2,%3};"               \
        : "+f"((d)[0]), "+f"((d)[1]), "+f"((d)[2]), "+f"((d)[3])              \
        : "r"(a0), "r"(a1), "r"(a2), "r"(a3), "r"(b0), "r"(b1))

#define LDSM_X4(r0, r1, r2, r3, addr)                                         \
    asm volatile("ldmatrix.sync.aligned.m8n8.x4.shared.b16 {%0,%1,%2,%3}, [%4];" \
        : "=r"(r0), "=r"(r1), "=r"(r2), "=r"(r3) : "r"(addr))

#define CP_ASYNC16(dst, src)                                                  \
    asm volatile("cp.async.ca.shared.global [%0], [%1], 16;"                  \
        :: "r"(dst), "l"(src) : "memory")
#define CP_COMMIT()  asm volatile("cp.async.commit_group;" ::: "memory")
#define CP_WAIT0()   asm volatile("cp.async.wait_group 0;" ::: "memory")

// ---------------------------------------------------------------------------
// Merged setup: block 0 builds the CSR, blocks 1..32 split W2^T to bf16 hi/lo.
// ---------------------------------------------------------------------------
__global__ void __launch_bounds__(512)
setup_all(const void* __restrict__ eiv, int E, const float* __restrict__ W2) {
    const int t = threadIdx.x;

    if (blockIdx.x > 0) {
        int i = (blockIdx.x - 1) * 512 + t;
        if (i < NOUT * HID) {
            int n = i >> 6, k = i & 63;
            float f = W2[k * NOUT + n];
            __nv_bfloat16 h = __float2bfloat16(f);
            __nv_bfloat16 l = __float2bfloat16(f - __bfloat162float(h));
            g_w2t_hi[i] = h;
            g_w2t_lo[i] = l;
        }
        return;
    }

    // ---- block 0: CSR of normalized adjacency ----
    const int*       e32 = (const int*)eiv;
    const long long* e64 = (const long long*)eiv;

    __shared__ int   s_odd;
    __shared__ int   s_src[MAX_E];
    __shared__ int   s_dst[MAX_E];
    __shared__ int   s_deg[NJ];
    __shared__ float s_dis[NJ];
    __shared__ int   s_off[NJ + 1];

    if (t == 0) s_odd = 0;
    __syncthreads();
    {
        int local = 0;
        for (int i = 2 * t + 1; i < 2 * E; i += 2 * blockDim.x)
            local |= (e32[i] != 0);
        if (local) atomicOr(&s_odd, 1);
    }
    __syncthreads();
    const int is64 = !s_odd;

    for (int i = t; i < E; i += blockDim.x) {
        int sv, dv;
        if (is64) { sv = (int)e64[i]; dv = (int)e64[E + i]; }
        else      { sv = e32[i];      dv = e32[E + i]; }
        s_src[i] = clampj(sv);
        s_dst[i] = clampj(dv);
    }
    for (int j = t; j < NJ; j += blockDim.x) s_deg[j] = 1;  // self loop
    __syncthreads();
    for (int i = t; i < E; i += blockDim.x) atomicAdd(&s_deg[s_dst[i]], 1);
    __syncthreads();
    if (t == 0) {
        int acc = 0;
        for (int j = 0; j < NJ; j++) { s_off[j] = acc; acc += s_deg[j]; }
        s_off[NJ] = acc;
    }
    for (int j = t; j < NJ; j += blockDim.x) s_dis[j] = rsqrtf((float)s_deg[j]);
    __syncthreads();
    if (t < NJ) {
        int p = s_off[t];
        float dj = s_dis[t];
        for (int e = 0; e < E; e++) {
            if (s_dst[e] == t) {
                int se = s_src[e];
                g_csr_src[p] = se;
                g_csr_w[p]   = s_dis[se] * dj;
                p++;
            }
        }
        g_csr_src[p] = t;               // self loop last (reference order)
        g_csr_w[p]   = dj * dj;
    }
    for (int j = t; j <= NJ; j += blockDim.x) g_csr_off[j] = s_off[j];
}

// ---------------------------------------------------------------------------
// Part A (per-graph CTA): ah1 = A * gelu((A*x) W1 + b1), split to bf16 hi/lo.
// ---------------------------------------------------------------------------
__global__ void __launch_bounds__(256)
gcn_partA(const float* __restrict__ x,
          const float* __restrict__ W1, const float* __restrict__ b1,
          int nTot) {
    __shared__ __align__(16) float s_x  [NJ * DIN];
    __shared__ __align__(16) float s_ax [NJ * DIN];
    __shared__ __align__(16) float s_h1 [NJ * HID];
    __shared__ __align__(16) float s_ah1[NJ * HID];
    __shared__ __align__(16) float s_W1 [DIN * HID];
    __shared__ __align__(16) float s_b1 [HID];
    __shared__ int s_off[NJ + 1];
    __shared__ int s_src[MAX_T];
    __shared__ __align__(16) float s_w[MAX_T];

    const int t = threadIdx.x;
    const int g = blockIdx.x;

    const float* xg = x + (size_t)g * (NJ * DIN);
    for (int i = t; i < NJ * DIN; i += 256) s_x[i] = xg[i];
    for (int i = t; i < DIN * HID; i += 256) s_W1[i] = W1[i];
    if (t < HID) s_b1[t] = b1[t];
    for (int i = t; i <= NJ; i += 256) s_off[i] = g_csr_off[i];
    for (int i = t; i < nTot; i += 256) { s_src[i] = g_csr_src[i]; s_w[i] = g_csr_w[i]; }
    __syncthreads();

    for (int idx = t; idx < NJ * DIN; idx += 256) {
        int j = idx / DIN, d = idx - j * DIN;
        float acc = 0.f;
        int e0 = s_off[j], e1 = s_off[j + 1];
        for (int e = e0; e < e1; e++) acc += s_w[e] * s_x[s_src[e] * DIN + d];
        s_ax[idx] = acc;
    }
    __syncthreads();

    for (int idx = t; idx < NJ * HID; idx += 256) {
        int j = idx >> 6, k = idx & 63;
        float v = fmaf(s_ax[j * DIN + 0], s_W1[k],
                  fmaf(s_ax[j * DIN + 1], s_W1[HID + k],
                  fmaf(s_ax[j * DIN + 2], s_W1[2 * HID + k], s_b1[k])));
        s_h1[idx] = gelu_fast(v);
    }
    __syncthreads();

    for (int idx = t; idx < NJ * HID; idx += 256) {
        int j = idx >> 6, k = idx & 63;
        float acc = 0.f;
        int e0 = s_off[j], e1 = s_off[j + 1];
        for (int e = e0; e < e1; e++) acc += s_w[e] * s_h1[(s_src[e] << 6) + k];
        s_ah1[idx] = acc;
    }
    __syncthreads();

    const size_t base = (size_t)g * (NJ * HID);
    for (int i = t; i < NJ * HID; i += 256) {
        float f = s_ah1[i];
        __nv_bfloat16 h = __float2bfloat16(f);
        __nv_bfloat16 l = __float2bfloat16(f - __bfloat162float(h));
        g_ah_hi[base + i] = h;
        g_ah_lo[base + i] = l;
    }
}

// ---------------------------------------------------------------------------
// Part B: out = gelu(AH1 @ W2 + b2), warp mma.sync, 3-term hi/lo comp.
// Persistent CTAs: TPC=8 m-tiles each, one 128-col n-half, B loaded once.
// SMEM: B is staged through the A stage-1 buffers (dead after register
// hoist) -> 74KB/CTA -> 3 CTAs/SM.
// ---------------------------------------------------------------------------
#define STRD   36
#define TILE_BYTES (128 * STRD * 4)                 // 18432
#define SM_B2  0
#define SM_A0  512                                  // stage0: hi, lo
#define SM_A1  (SM_A0 + 2 * TILE_BYTES)             // stage1: hi, lo (B staged here first)
#define SMB_TOTAL (SM_A1 + 2 * TILE_BYTES)          // 74240

__device__ __forceinline__ void prefetch_A(uint32_t stage, long r0, int t) {
#pragma unroll
    for (int i = 0; i < 4; i++) {
        int c = t + 256 * i;
        int row = c >> 3, seg = c & 7;
        uint32_t dst = stage + row * (STRD * 4) + seg * 16;
        CP_ASYNC16(dst,              (const char*)(g_ah_hi + (r0 + row) * HID + seg * 8));
        CP_ASYNC16(dst + TILE_BYTES, (const char*)(g_ah_lo + (r0 + row) * HID + seg * 8));
    }
}

__global__ void __launch_bounds__(256)
gemm_gelu(const float* __restrict__ b2, float* __restrict__ out, int Mtotal) {
    extern __shared__ __align__(16) char smem[];
    float* b2s = (float*)(smem + SM_B2);

    const int t   = threadIdx.x;
    const int wid = t >> 5;
    const int lid = t & 31;
    const int gq  = lid >> 2;
    const int tq  = lid & 3;
    const int blk = blockIdx.x >> 1;        // m-block (TPC tiles)
    const int nh  = blockIdx.x & 1;         // n half
    const int c0  = nh * 128;
    const long mt0 = (long)blk * TPC;

    const uint32_t sb = smem_u32(smem);

    // ---- B staged into stage-1 buffers; A tile 0 into stage-0 ----
#pragma unroll
    for (int i = 0; i < 4; i++) {
        int c = t + 256 * i;
        int row = c >> 3, seg = c & 7;
        uint32_t dst = sb + SM_A1 + row * (STRD * 4) + seg * 16;
        CP_ASYNC16(dst,              (const char*)(g_w2t_hi + (c0 + row) * HID + seg * 8));
        CP_ASYNC16(dst + TILE_BYTES, (const char*)(g_w2t_lo + (c0 + row) * HID + seg * 8));
    }
    prefetch_A(sb + SM_A0, mt0 * 128, t);
    CP_COMMIT();
    if (t < 128) b2s[t] = b2[c0 + t];
    CP_WAIT0();
    __syncthreads();

    // ---- per-lane ldmatrix offset (x4): conflict-free with STRD=36 ----
    const uint32_t frag_row = (lid & 7) + ((lid >> 3) & 1) * 8;
    const uint32_t frag_k   = (lid >> 4) * 4;
    const uint32_t frag_off = (frag_row * STRD + frag_k) * 4;

    const int colbase = wid * 16;

    // ---- hoist B fragments (CTA-invariant) from the staged region ----
    uint32_t bh[4][4], bl[4][4];
    {
        const uint32_t bb_h = sb + SM_A1 + colbase * STRD * 4 + frag_off;
        const uint32_t bb_l = bb_h + TILE_BYTES;
#pragma unroll
        for (int q = 0; q < 4; q++) {
            LDSM_X4(bh[q][0], bh[q][1], bh[q][2], bh[q][3], bb_h + q * 32);
            LDSM_X4(bl[q][0], bl[q][1], bl[q][2], bl[q][3], bb_l + q * 32);
        }
    }
    __syncthreads();   // everyone done reading B before stage-1 is reused for A

    for (int it = 0; it < TPC; it++) {
        if (it + 1 < TPC) {
            uint32_t stage = sb + (((it + 1) & 1) ? SM_A1 : SM_A0);
            prefetch_A(stage, (mt0 + it + 1) * 128, t);
            CP_COMMIT();
        }

        const uint32_t abase = sb + ((it & 1) ? SM_A1 : SM_A0) + frag_off;
        const long r0 = (mt0 + it) * 128;

        for (int m = 0; m < 8; m++) {
            float acch[2][4], accl[2][4];
#pragma unroll
            for (int n = 0; n < 2; n++)
#pragma unroll
                for (int v = 0; v < 4; v++) { acch[n][v] = 0.f; accl[n][v] = 0.f; }

            const uint32_t am = m * 16 * STRD * 4;
#pragma unroll
            for (int q = 0; q < 4; q++) {
                uint32_t ah0, ah1, ah2, ah3, al0, al1, al2, al3;
                LDSM_X4(ah0, ah1, ah2, ah3, abase + am + q * 32);
                LDSM_X4(al0, al1, al2, al3, abase + TILE_BYTES + am + q * 32);
#pragma unroll
                for (int n = 0; n < 2; n++) {
                    MMA_BF16(acch[n], ah0, ah1, ah2, ah3, bh[q][n], bh[q][2 + n]);
                    MMA_BF16(acch[n], al0, al1, al2, al3, bh[q][n], bh[q][2 + n]);
                    MMA_BF16(accl[n], ah0, ah1, ah2, ah3, bl[q][n], bl[q][2 + n]);
                }
            }

            const long ra0 = r0 + m * 16 + gq;
            const long ra1 = ra0 + 8;
#pragma unroll
            for (int n = 0; n < 2; n++) {
                const int lc = colbase + n * 8 + 2 * tq;
                const float bb0 = b2s[lc], bb1 = b2s[lc + 1];
                float2 o0, o1;
                o0.x = gelu_fast(acch[n][0] + accl[n][0] + bb0);
                o0.y = gelu_fast(acch[n][1] + accl[n][1] + bb1);
                o1.x = gelu_fast(acch[n][2] + accl[n][2] + bb0);
                o1.y = gelu_fast(acch[n][3] + accl[n][3] + bb1);
                *(float2*)(out + ra0 * NOUT + c0 + lc) = o0;
                *(float2*)(out + ra1 * NOUT + c0 + lc) = o1;
            }
        }

        if (it + 1 < TPC) { CP_WAIT0(); __syncthreads(); }
    }
}

// ---------------------------------------------------------------------------
extern "C" void kernel_launch(void* const* d_in, const int* in_sizes, int n_in,
                              void* d_out, int out_size) {
    const float* x  = (const float*)d_in[0];
    const void*  ei = d_in[1];                    // int32 or int64 (2,E)
    const float* W1 = (const float*)d_in[2];
    const float* b1 = (const float*)d_in[3];
    const float* W2 = (const float*)d_in[4];
    const float* b2 = (const float*)d_in[5];
    float* out = (float*)d_out;

    const int E  = in_sizes[1] / 2;               // 300
    const int nG = in_sizes[0] / (NJ * DIN);      // 2048
    const int nTot = E + NJ;                      // 375
    const int Mtotal = nG * NJ;                   // 153600
    const int tiles = Mtotal / 128;               // 1200 (exact)
    const int blocks = (tiles / TPC) * 2;         // 300

    cudaFuncSetAttribute(gemm_gelu, cudaFuncAttributeMaxDynamicSharedMemorySize,
                         SMB_TOTAL);

    setup_all<<<33, 512>>>(ei, E, W2);
    gcn_partA<<<nG, 256>>>(x, W1, b1, nTot);
    gemm_gelu<<<blocks, 256, SMB_TOTAL>>>(b2, out, Mtotal);
}

// round 16
// speedup vs baseline: 1.4940x; 1.0179x over previous
#include <cuda_runtime.h>
#include <cuda_bf16.h>
#include <math.h>
#include <stdint.h>

// Problem constants: B=16,T=128 -> 2048 graphs; J=75; 3->64->256; E=300.
#define NJ    75
#define DIN   3
#define HID   64
#define NOUT  256
#define MAX_E 1024
#define MAX_T 544
#define MAXG  2048
#define TPC   6        // m-tiles per CTA in gemm_gelu (grid 400 -> 2.7 CTA/SM)

// ---------------- persistent device scratch ----------------
__device__ int   g_csr_src[MAX_T];
__device__ float g_csr_w[MAX_T];
__device__ int   g_csr_off[NJ + 1];
__device__ __nv_bfloat16 g_ah_hi[MAXG * NJ * HID];   // ah1 split hi [row][k]
__device__ __nv_bfloat16 g_ah_lo[MAXG * NJ * HID];   // ah1 split lo
__device__ __nv_bfloat16 g_w2t_hi[NOUT * HID];       // W2^T split hi [n][k]
__device__ __nv_bfloat16 g_w2t_lo[NOUT * HID];       // W2^T split lo

// ---------------- math helpers ----------------
__device__ __forceinline__ float gelu_fast(float v) {
    const float x  = v * 0.70710678118654752f;
    const float ax = fabsf(x);
    const float den = fmaf(0.3275911f, ax, 1.0f);
    float t;
    asm("rcp.approx.f32 %0, %1;" : "=f"(t) : "f"(den));
    float p = fmaf(1.061405429f, t, -1.453152027f);
    p = fmaf(p, t, 1.421413741f);
    p = fmaf(p, t, -0.284496736f);
    p = fmaf(p, t, 0.254829592f);
    p = p * t;
    const float ex   = __expf(-x * x);
    const float erfa = fmaf(-p, ex, 1.0f);
    return 0.5f * v * (1.0f + copysignf(erfa, x));
}
__device__ __forceinline__ int clampj(int v) {
    return v < 0 ? 0 : (v >= NJ ? NJ - 1 : v);
}
__device__ __forceinline__ uint32_t smem_u32(const void* p) {
    uint32_t a;
    asm("{ .reg .u64 t; cvta.to.shared.u64 t, %1; cvt.u32.u64 %0, t; }"
        : "=r"(a) : "l"(p));
    return a;
}

// Warp-level bf16 MMA + ldmatrix + cp.async (sm_80/75 PTX, legal on sm_103).
#define MMA_BF16(d, a0, a1, a2, a3, b0, b1)                                   \
    asm volatile("mma.sync.aligned.m16n8k16.row.col.f32.bf16.bf16.f32 "       \
        "{%0,%1,%2,%3}, {%4,%5,%6,%7}, {%8,%9}, {%0,%1,%2,%3};"               \
        : "+f"((d)[0]), "+f"((d)[1]), "+f"((d)[2]), "+f"((d)[3])              \
        : "r"(a0), "r"(a1), "r"(a2), "r"(a3), "r"(b0), "r"(b1))

#define LDSM_X4(r0, r1, r2, r3, addr)                                         \
    asm volatile("ldmatrix.sync.aligned.m8n8.x4.shared.b16 {%0,%1,%2,%3}, [%4];" \
        : "=r"(r0), "=r"(r1), "=r"(r2), "=r"(r3) : "r"(addr))

#define CP_ASYNC16(dst, src)                                                  \
    asm volatile("cp.async.ca.shared.global [%0], [%1], 16;"                  \
        :: "r"(dst), "l"(src) : "memory")
#define CP_COMMIT()  asm volatile("cp.async.commit_group;" ::: "memory")
#define CP_WAIT0()   asm volatile("cp.async.wait_group 0;" ::: "memory")

// ---------------------------------------------------------------------------
// Merged setup: block 0 builds the CSR (rank-based parallel fill, one thread
// per EDGE -> deterministic, no per-dst serial scan); blocks 1..32 split W2^T.
// ---------------------------------------------------------------------------
__global__ void __launch_bounds__(512)
setup_all(const void* __restrict__ eiv, int E, const float* __restrict__ W2) {
    const int t = threadIdx.x;

    if (blockIdx.x > 0) {
        int i = (blockIdx.x - 1) * 512 + t;
        if (i < NOUT * HID) {
            int n = i >> 6, k = i & 63;
            float f = W2[k * NOUT + n];
            __nv_bfloat16 h = __float2bfloat16(f);
            __nv_bfloat16 l = __float2bfloat16(f - __bfloat162float(h));
            g_w2t_hi[i] = h;
            g_w2t_lo[i] = l;
        }
        return;
    }

    // ---- block 0: CSR of normalized adjacency ----
    const int*       e32 = (const int*)eiv;
    const long long* e64 = (const long long*)eiv;

    __shared__ int   s_odd;
    __shared__ int   s_src[MAX_E];
    __shared__ int   s_dst[MAX_E];
    __shared__ int   s_deg[NJ];
    __shared__ float s_dis[NJ];
    __shared__ int   s_off[NJ + 1];

    if (t == 0) s_odd = 0;
    __syncthreads();
    {
        int local = 0;
        for (int i = 2 * t + 1; i < 2 * E; i += 2 * blockDim.x)
            local |= (e32[i] != 0);
        if (local) atomicOr(&s_odd, 1);
    }
    __syncthreads();
    const int is64 = !s_odd;

    for (int i = t; i < E; i += blockDim.x) {
        int sv, dv;
        if (is64) { sv = (int)e64[i]; dv = (int)e64[E + i]; }
        else      { sv = e32[i];      dv = e32[E + i]; }
        s_src[i] = clampj(sv);
        s_dst[i] = clampj(dv);
    }
    for (int j = t; j < NJ; j += blockDim.x) s_deg[j] = 1;  // self loop
    __syncthreads();
    for (int i = t; i < E; i += blockDim.x) atomicAdd(&s_deg[s_dst[i]], 1);
    __syncthreads();
    if (t == 0) {
        int acc = 0;
        for (int j = 0; j < NJ; j++) { s_off[j] = acc; acc += s_deg[j]; }
        s_off[NJ] = acc;
    }
    for (int j = t; j < NJ; j += blockDim.x) s_dis[j] = rsqrtf((float)s_deg[j]);
    __syncthreads();

    // rank-based fill: thread t handles edge t; rank = #earlier edges w/ same dst
    if (t < E) {
        const int d = s_dst[t];
        int rank = 0;
        for (int e = 0; e < t; e++) rank += (s_dst[e] == d);
        const int se = s_src[t];
        const int p  = s_off[d] + rank;
        g_csr_src[p] = se;
        g_csr_w[p]   = s_dis[se] * s_dis[d];
    }
    // self loop at the last slot of each node's segment
    if (t < NJ) {
        const int p = s_off[t + 1] - 1;
        g_csr_src[p] = t;
        g_csr_w[p]   = s_dis[t] * s_dis[t];
    }
    for (int j = t; j <= NJ; j += blockDim.x) g_csr_off[j] = s_off[j];
}

// ---------------------------------------------------------------------------
// Part A (per-graph CTA): ah1 = A * gelu((A*x) W1 + b1), split to bf16 hi/lo.
// ---------------------------------------------------------------------------
__global__ void __launch_bounds__(256)
gcn_partA(const float* __restrict__ x,
          const float* __restrict__ W1, const float* __restrict__ b1,
          int nTot) {
    __shared__ __align__(16) float s_x  [NJ * DIN];
    __shared__ __align__(16) float s_ax [NJ * DIN];
    __shared__ __align__(16) float s_h1 [NJ * HID];
    __shared__ __align__(16) float s_ah1[NJ * HID];
    __shared__ __align__(16) float s_W1 [DIN * HID];
    __shared__ __align__(16) float s_b1 [HID];
    __shared__ int s_off[NJ + 1];
    __shared__ int s_src[MAX_T];
    __shared__ __align__(16) float s_w[MAX_T];

    const int t = threadIdx.x;
    const int g = blockIdx.x;

    const float* xg = x + (size_t)g * (NJ * DIN);
    for (int i = t; i < NJ * DIN; i += 256) s_x[i] = xg[i];
    for (int i = t; i < DIN * HID; i += 256) s_W1[i] = W1[i];
    if (t < HID) s_b1[t] = b1[t];
    for (int i = t; i <= NJ; i += 256) s_off[i] = g_csr_off[i];
    for (int i = t; i < nTot; i += 256) { s_src[i] = g_csr_src[i]; s_w[i] = g_csr_w[i]; }
    __syncthreads();

    for (int idx = t; idx < NJ * DIN; idx += 256) {
        int j = idx / DIN, d = idx - j * DIN;
        float acc = 0.f;
        int e0 = s_off[j], e1 = s_off[j + 1];
        for (int e = e0; e < e1; e++) acc += s_w[e] * s_x[s_src[e] * DIN + d];
        s_ax[idx] = acc;
    }
    __syncthreads();

    for (int idx = t; idx < NJ * HID; idx += 256) {
        int j = idx >> 6, k = idx & 63;
        float v = fmaf(s_ax[j * DIN + 0], s_W1[k],
                  fmaf(s_ax[j * DIN + 1], s_W1[HID + k],
                  fmaf(s_ax[j * DIN + 2], s_W1[2 * HID + k], s_b1[k])));
        s_h1[idx] = gelu_fast(v);
    }
    __syncthreads();

    for (int idx = t; idx < NJ * HID; idx += 256) {
        int j = idx >> 6, k = idx & 63;
        float acc = 0.f;
        int e0 = s_off[j], e1 = s_off[j + 1];
        for (int e = e0; e < e1; e++) acc += s_w[e] * s_h1[(s_src[e] << 6) + k];
        s_ah1[idx] = acc;
    }
    __syncthreads();

    const size_t base = (size_t)g * (NJ * HID);
    for (int i = t; i < NJ * HID; i += 256) {
        float f = s_ah1[i];
        __nv_bfloat16 h = __float2bfloat16(f);
        __nv_bfloat16 l = __float2bfloat16(f - __bfloat162float(h));
        g_ah_hi[base + i] = h;
        g_ah_lo[base + i] = l;
    }
}

// ---------------------------------------------------------------------------
// Part B: out = gelu(AH1 @ W2 + b2), warp mma.sync, 3-term hi/lo comp.
// Persistent CTAs: TPC m-tiles each, one 128-col n-half, B loaded once
// (staged via the A stage-1 buffers). 74KB/CTA -> 3 CTAs/SM; grid 400.
// ---------------------------------------------------------------------------
#define STRD   36
#define TILE_BYTES (128 * STRD * 4)                 // 18432
#define SM_B2  0
#define SM_A0  512                                  // stage0: hi, lo
#define SM_A1  (SM_A0 + 2 * TILE_BYTES)             // stage1 (B staged here first)
#define SMB_TOTAL (SM_A1 + 2 * TILE_BYTES)          // 74240

__device__ __forceinline__ void prefetch_A(uint32_t stage, long r0, int t) {
#pragma unroll
    for (int i = 0; i < 4; i++) {
        int c = t + 256 * i;
        int row = c >> 3, seg = c & 7;
        uint32_t dst = stage + row * (STRD * 4) + seg * 16;
        CP_ASYNC16(dst,              (const char*)(g_ah_hi + (r0 + row) * HID + seg * 8));
        CP_ASYNC16(dst + TILE_BYTES, (const char*)(g_ah_lo + (r0 + row) * HID + seg * 8));
    }
}

__global__ void __launch_bounds__(256)
gemm_gelu(const float* __restrict__ b2, float* __restrict__ out, int Mtotal) {
    extern __shared__ __align__(16) char smem[];
    float* b2s = (float*)(smem + SM_B2);

    const int t   = threadIdx.x;
    const int wid = t >> 5;
    const int lid = t & 31;
    const int gq  = lid >> 2;
    const int tq  = lid & 3;
    const int blk = blockIdx.x >> 1;        // m-block (TPC tiles)
    const int nh  = blockIdx.x & 1;         // n half
    const int c0  = nh * 128;
    const long mt0 = (long)blk * TPC;

    const uint32_t sb = smem_u32(smem);

    // ---- B staged into stage-1 buffers; A tile 0 into stage-0 ----
#pragma unroll
    for (int i = 0; i < 4; i++) {
        int c = t + 256 * i;
        int row = c >> 3, seg = c & 7;
        uint32_t dst = sb + SM_A1 + row * (STRD * 4) + seg * 16;
        CP_ASYNC16(dst,              (const char*)(g_w2t_hi + (c0 + row) * HID + seg * 8));
        CP_ASYNC16(dst + TILE_BYTES, (const char*)(g_w2t_lo + (c0 + row) * HID + seg * 8));
    }
    prefetch_A(sb + SM_A0, mt0 * 128, t);
    CP_COMMIT();
    if (t < 128) b2s[t] = b2[c0 + t];
    CP_WAIT0();
    __syncthreads();

    // ---- per-lane ldmatrix offset (x4): conflict-free with STRD=36 ----
    const uint32_t frag_row = (lid & 7) + ((lid >> 3) & 1) * 8;
    const uint32_t frag_k   = (lid >> 4) * 4;
    const uint32_t frag_off = (frag_row * STRD + frag_k) * 4;

    const int colbase = wid * 16;

    // ---- hoist B fragments (CTA-invariant) from the staged region ----
    uint32_t bh[4][4], bl[4][4];
    {
        const uint32_t bb_h = sb + SM_A1 + colbase * STRD * 4 + frag_off;
        const uint32_t bb_l = bb_h + TILE_BYTES;
#pragma unroll
        for (int q = 0; q < 4; q++) {
            LDSM_X4(bh[q][0], bh[q][1], bh[q][2], bh[q][3], bb_h + q * 32);
            LDSM_X4(bl[q][0], bl[q][1], bl[q][2], bl[q][3], bb_l + q * 32);
        }
    }
    __syncthreads();   // B fully read before stage-1 is reused for A

    for (int it = 0; it < TPC; it++) {
        if (it + 1 < TPC) {
            uint32_t stage = sb + (((it + 1) & 1) ? SM_A1 : SM_A0);
            prefetch_A(stage, (mt0 + it + 1) * 128, t);
            CP_COMMIT();
        }

        const uint32_t abase = sb + ((it & 1) ? SM_A1 : SM_A0) + frag_off;
        const long r0 = (mt0 + it) * 128;

        for (int m = 0; m < 8; m++) {
            float acch[2][4], accl[2][4];
#pragma unroll
            for (int n = 0; n < 2; n++)
#pragma unroll
                for (int v = 0; v < 4; v++) { acch[n][v] = 0.f; accl[n][v] = 0.f; }

            const uint32_t am = m * 16 * STRD * 4;
#pragma unroll
            for (int q = 0; q < 4; q++) {
                uint32_t ah0, ah1, ah2, ah3, al0, al1, al2, al3;
                LDSM_X4(ah0, ah1, ah2, ah3, abase + am + q * 32);
                LDSM_X4(al0, al1, al2, al3, abase + TILE_BYTES + am + q * 32);
#pragma unroll
                for (int n = 0; n < 2; n++) {
                    MMA_BF16(acch[n], ah0, ah1, ah2, ah3, bh[q][n], bh[q][2 + n]);
                    MMA_BF16(acch[n], al0, al1, al2, al3, bh[q][n], bh[q][2 + n]);
                    MMA_BF16(accl[n], ah0, ah1, ah2, ah3, bl[q][n], bl[q][2 + n]);
                }
            }

            const long ra0 = r0 + m * 16 + gq;
            const long ra1 = ra0 + 8;
#pragma unroll
            for (int n = 0; n < 2; n++) {
                const int lc = colbase + n * 8 + 2 * tq;
                const float bb0 = b2s[lc], bb1 = b2s[lc + 1];
                float2 o0, o1;
                o0.x = gelu_fast(acch[n][0] + accl[n][0] + bb0);
                o0.y = gelu_fast(acch[n][1] + accl[n][1] + bb1);
                o1.x = gelu_fast(acch[n][2] + accl[n][2] + bb0);
                o1.y = gelu_fast(acch[n][3] + accl[n][3] + bb1);
                *(float2*)(out + ra0 * NOUT + c0 + lc) = o0;
                *(float2*)(out + ra1 * NOUT + c0 + lc) = o1;
            }
        }

        if (it + 1 < TPC) { CP_WAIT0(); __syncthreads(); }
    }
}

// ---------------------------------------------------------------------------
extern "C" void kernel_launch(void* const* d_in, const int* in_sizes, int n_in,
                              void* d_out, int out_size) {
    const float* x  = (const float*)d_in[0];
    const void*  ei = d_in[1];                    // int32 or int64 (2,E)
    const float* W1 = (const float*)d_in[2];
    const float* b1 = (const float*)d_in[3];
    const float* W2 = (const float*)d_in[4];
    const float* b2 = (const float*)d_in[5];
    float* out = (float*)d_out;

    const int E  = in_sizes[1] / 2;               // 300
    const int nG = in_sizes[0] / (NJ * DIN);      // 2048
    const int nTot = E + NJ;                      // 375
    const int Mtotal = nG * NJ;                   // 153600
    const int tiles = Mtotal / 128;               // 1200 (exact)
    const int blocks = (tiles / TPC) * 2;         // 400

    cudaFuncSetAttribute(gemm_gelu, cudaFuncAttributeMaxDynamicSharedMemorySize,
                         SMB_TOTAL);

    setup_all<<<33, 512>>>(ei, E, W2);
    gcn_partA<<<nG, 256>>>(x, W1, b1, nTot);
    gemm_gelu<<<blocks, 256, SMB_TOTAL>>>(b2, out, Mtotal);
}